// round 2
// baseline (speedup 1.0000x reference)
#include <cuda_runtime.h>
#include <utility>

#define BLK 128   // 8 chains x 16 heads

// ---- compile-time Cl(4,1) Cayley sign: metric (+,+,+,+,-) on bits 0..4 ----
constexpr __host__ __device__ int popc5(int x) {
    int c = 0;
    for (int i = 0; i < 6; i++) c += (x >> i) & 1;
    return c;
}
constexpr __host__ __device__ bool cneg(int a, int b) {
    int s = 0;
    for (int t = a >> 1; t; t >>= 1) s += popc5(t & b);
    bool neg = (s & 1) != 0;
    if ((a & b) & 0x10) neg = !neg;   // e5^2 = -1
    return neg;
}

// geometric product: acc[k] = sum_a sign(a, a^k) * dr[a] * psi[a^k]
// row a = 0 initializes (sign +1, a^k = k)
template<int... Ks>
__device__ __forceinline__ void gp_row0(float dra, const float (&psi)[32], float (&acc)[32],
                                        std::integer_sequence<int, Ks...>) {
    ((acc[Ks] = dra * psi[Ks]), ...);
}

template<int A, int K, bool NEG>
struct GPTerm {
    static __device__ __forceinline__ void run(float dra, const float (&psi)[32], float (&acc)[32]) {
        if constexpr (NEG) acc[K] = fmaf(-dra, psi[A ^ K], acc[K]);
        else               acc[K] = fmaf( dra, psi[A ^ K], acc[K]);
    }
};

template<int A, int... Ks>
__device__ __forceinline__ void gp_row(float dra, const float (&psi)[32], float (&acc)[32],
                                       std::integer_sequence<int, Ks...>) {
    (GPTerm<A, Ks, cneg(A, A ^ Ks)>::run(dra, psi, acc), ...);
}
template<int... As>
__device__ __forceinline__ void gp_all(const float (&dr)[32], const float (&psi)[32], float (&acc)[32],
                                       std::integer_sequence<int, As...>) {
    (gp_row<As + 1>(dr[As + 1], psi, acc, std::make_integer_sequence<int, 32>{}), ...);
}

// shapes: B=16, S=256, N=64, D=6, H=16
// x strides (floats): b: 98304, s: 384, n: 6
__global__ __launch_bounds__(BLK)
void versor_kernel(const float* __restrict__ x,
                   const float* __restrict__ Win,    // [6,512]
                   const float* __restrict__ bin,    // [512]
                   const float* __restrict__ Wout,   // [512,6]
                   const float* __restrict__ bout,   // [6]
                   float* __restrict__ out)
{
    // padded shared: per-head stride 196 (196 % 32 == 4 -> conflict-free 4-head broadcast)
    __shared__ __align__(16) float sWin[16 * 196];   // [h][d][c]
    __shared__ __align__(16) float sWout[16 * 196];  // [h][d][c]
    __shared__ __align__(16) float sBin[16 * 36];    // [h][c]
    __shared__ float sPart[2][16][50];               // double-buffered head partials [buf][h][ci*6+d]

    const int tid = threadIdx.x;
    const int ci  = tid & 7;        // chain within block
    const int h   = tid >> 3;       // head
    const int b   = blockIdx.x >> 3;
    const int n0  = (blockIdx.x & 7) * 8;

    // ---- stage weights into shared (one-time) ----
    for (int i = tid; i < 3072; i += BLK) {            // Win[d][512]
        int d = i / 512, rem = i - d * 512;
        int hh = rem >> 5, c = rem & 31;
        sWin[hh * 196 + d * 32 + c] = Win[i];
    }
    for (int i = tid; i < 3072; i += BLK) {            // Wout[row][6] -> [h][d][c]
        int row = i / 6, d = i - row * 6;
        int hh = row >> 5, c = row & 31;
        sWout[hh * 196 + d * 32 + c] = Wout[i];
    }
    for (int i = tid; i < 512; i += BLK)
        sBin[(i >> 5) * 36 + (i & 31)] = bin[i];
    __syncthreads();

    const float* xchain = x + (size_t)b * 98304 + (size_t)(n0 + ci) * 6;
    const float* wi = sWin  + h * 196;
    const float* wo = sWout + h * 196;
    const float* bi = sBin  + h * 36;

    // reducer role (threads 0..47): chain rci, component rd
    const int  rci = tid / 6;
    const int  rd  = tid - rci * 6;
    const bool is_red = (tid < 48);
    const float boutr = __ldg(bout + (is_red ? rd : 0));
    const size_t obase = (size_t)b * 98304 + (size_t)(n0 + (is_red ? rci : 0)) * 6 + rd;

    // psi state in registers
    float psi[32];
#pragma unroll
    for (int k = 0; k < 32; k++) psi[k] = 0.0f;
    psi[0] = 1.0f;

    for (int t = 0; t < 256; t++) {
        // ---- load x_t[6] ----
        const float* xp = xchain + t * 384;
        float xv[6];
#pragma unroll
        for (int d = 0; d < 6; d++) xv[d] = __ldg(xp + d);

        // ---- embed: u = b_in + x @ W_in (this head's 32 cols) ----
        float u[32];
#pragma unroll
        for (int c4 = 0; c4 < 8; c4++) {
            float4 bb = *(const float4*)(bi + c4 * 4);
            u[c4 * 4 + 0] = bb.x; u[c4 * 4 + 1] = bb.y;
            u[c4 * 4 + 2] = bb.z; u[c4 * 4 + 3] = bb.w;
        }
#pragma unroll
        for (int d = 0; d < 6; d++) {
            float xd = xv[d];
#pragma unroll
            for (int c4 = 0; c4 < 8; c4++) {
                float4 w = *(const float4*)(wi + d * 32 + c4 * 4);
                u[c4 * 4 + 0] = fmaf(xd, w.x, u[c4 * 4 + 0]);
                u[c4 * 4 + 1] = fmaf(xd, w.y, u[c4 * 4 + 1]);
                u[c4 * 4 + 2] = fmaf(xd, w.z, u[c4 * 4 + 2]);
                u[c4 * 4 + 3] = fmaf(xd, w.w, u[c4 * 4 + 3]);
            }
        }

        // ---- delta_r = normalize(u + e0) ----
        u[0] += 1.0f;
        float s0 = 0.f, s1 = 0.f, s2 = 0.f, s3 = 0.f;
#pragma unroll
        for (int c = 0; c < 32; c += 4) {
            s0 = fmaf(u[c + 0], u[c + 0], s0);
            s1 = fmaf(u[c + 1], u[c + 1], s1);
            s2 = fmaf(u[c + 2], u[c + 2], s2);
            s3 = fmaf(u[c + 3], u[c + 3], s3);
        }
        float rn = rsqrtf((s0 + s1) + (s2 + s3) + 1e-12f);
#pragma unroll
        for (int c = 0; c < 32; c++) u[c] *= rn;

        // ---- psi = normalize(GP(dr, psi)) ----
        float acc[32];
        gp_row0(u[0], psi, acc, std::make_integer_sequence<int, 32>{});
        gp_all(u, psi, acc, std::make_integer_sequence<int, 31>{});

        s0 = s1 = s2 = s3 = 0.f;
#pragma unroll
        for (int c = 0; c < 32; c += 4) {
            s0 = fmaf(acc[c + 0], acc[c + 0], s0);
            s1 = fmaf(acc[c + 1], acc[c + 1], s1);
            s2 = fmaf(acc[c + 2], acc[c + 2], s2);
            s3 = fmaf(acc[c + 3], acc[c + 3], s3);
        }
        float rn2 = rsqrtf((s0 + s1) + (s2 + s3) + 1e-12f);
#pragma unroll
        for (int c = 0; c < 32; c++) psi[c] = acc[c] * rn2;

        // ---- projection partial: this head's 32 comps @ W_out[.,6] ----
        float pd[6];
#pragma unroll
        for (int d = 0; d < 6; d++) {
            float a0 = 0.f, a1 = 0.f, a2 = 0.f, a3 = 0.f;
#pragma unroll
            for (int c4 = 0; c4 < 8; c4++) {
                float4 w = *(const float4*)(wo + d * 32 + c4 * 4);
                a0 = fmaf(psi[c4 * 4 + 0], w.x, a0);
                a1 = fmaf(psi[c4 * 4 + 1], w.y, a1);
                a2 = fmaf(psi[c4 * 4 + 2], w.z, a2);
                a3 = fmaf(psi[c4 * 4 + 3], w.w, a3);
            }
            pd[d] = (a0 + a1) + (a2 + a3);
        }

        // ---- cross-head reduce (double-buffered, one barrier per step) ----
        float* pp = &sPart[t & 1][h][ci * 6];
#pragma unroll
        for (int d = 0; d < 6; d++) pp[d] = pd[d];
        __syncthreads();

        if (is_red) {
            float s = boutr;
#pragma unroll
            for (int hh = 0; hh < 16; hh++)
                s += sPart[t & 1][hh][rci * 6 + rd];
            float xvv = __ldg(x + obase + (size_t)t * 384);
            out[obase + (size_t)t * 384] = xvv + s;
        }
    }
}

extern "C" void kernel_launch(void* const* d_in, const int* in_sizes, int n_in,
                              void* d_out, int out_size)
{
    const float* x    = (const float*)d_in[0];
    const float* Win  = (const float*)d_in[1];
    const float* bin  = (const float*)d_in[2];
    const float* Wout = (const float*)d_in[3];
    const float* bout = (const float*)d_in[4];
    float* out = (float*)d_out;

    versor_kernel<<<128, BLK>>>(x, Win, bin, Wout, bout, out);
}